// round 3
// baseline (speedup 1.0000x reference)
#include <cuda_runtime.h>

#define BB 64
#define TT 256
#define HH 128
#define H4 512

// Precomputed enc_proj = enc_output @ W1, [B*T, H]  (8 MB scratch)
__device__ float g_ep[BB * TT * HH];

// ---------------- fast-but-accurate transcendentals (err ~5e-7 abs) --------
__device__ __forceinline__ float ex2f_(float x) {
    float y; asm("ex2.approx.ftz.f32 %0, %1;" : "=f"(y) : "f"(x)); return y;
}
__device__ __forceinline__ float rcpf_(float x) {
    float y; asm("rcp.approx.ftz.f32 %0, %1;" : "=f"(y) : "f"(x)); return y;
}
__device__ __forceinline__ float tanh_(float x) {
    // tanh(|x|) = 1 - 2/(e^{2|x|}+1); ex2/rcp approx are ~2^-22 accurate
    float ax = fabsf(x);
    float e  = ex2f_(ax * 2.8853900817779268f);   // 2*log2(e)
    float y  = fmaf(-2.0f, rcpf_(e + 1.0f), 1.0f);
    return copysignf(y, x);
}
__device__ __forceinline__ float sigm_(float x) {
    return rcpf_(1.0f + ex2f_(-1.4426950408889634f * x));
}

// ---------------- kernel 1: enc_proj = enc_output @ W1 ---------------------
__global__ void __launch_bounds__(128) encproj_k(const float* __restrict__ enc,
                                                 const float* __restrict__ W1) {
    __shared__ float rowbuf[32 * HH];          // 32 rows of enc
    int base = blockIdx.x * 32;                // row index in [0, B*T)
    const float4* src = (const float4*)(enc + (size_t)base * HH);
    float4* dst = (float4*)rowbuf;
    for (int i = threadIdx.x; i < 32 * HH / 4; i += 128) dst[i] = src[i];
    __syncthreads();
    int j = threadIdx.x;                       // output column
    for (int r = 0; r < 32; ++r) {
        float acc = 0.f;
        #pragma unroll 16
        for (int h = 0; h < HH; ++h)
            acc = fmaf(rowbuf[r * HH + h], __ldg(&W1[h * HH + j]), acc);
        g_ep[(size_t)(base + r) * HH + j] = acc;
    }
}

// ---------------- kernel 2: persistent per-batch decoder -------------------
struct DecodeSmem {
    float ep[TT * HH];    // 128 KB  enc_proj for this batch
    float W2s[HH * HH];   //  64 KB
    float Wks[2 * H4];    //   4 KB
    float bs[H4];
    float Vs[HH];
    float xs[TT * 2];
    float hs[HH];
    float cs[HH];
    float zp[4 * H4];     // z partials (4 k-quarters)
    float zs[H4];         // full gate pre-activations
    float ap[4 * HH];     // hW2 partials
    float aa[HH];         // a = h @ W2
    float sc[TT];         // scores
    float redv[16];
    int   redi[16];
    float smax;
    float sinv;
    float ptr0;
    float ptr1;
};

__global__ void __launch_bounds__(512, 1) decode_k(
    const float* __restrict__ x,   const float* __restrict__ h0,
    const float* __restrict__ c0,  const float* __restrict__ W2,
    const float* __restrict__ V,   const float* __restrict__ Wk,
    const float* __restrict__ Wr,  const float* __restrict__ bias,
    float* __restrict__ out)
{
    extern __shared__ float smraw[];
    DecodeSmem* s = (DecodeSmem*)smraw;

    const int b    = blockIdx.x;
    const int tid  = threadIdx.x;
    const int lane = tid & 31;
    const int warp = tid >> 5;

    // ---- prologue: stage everything reusable into SMEM (float4 copies) ----
    {
        const float4* epsrc = (const float4*)(g_ep + (size_t)b * TT * HH);
        float4* epdst = (float4*)s->ep;
        for (int i = tid; i < TT * HH / 4; i += 512) epdst[i] = epsrc[i];

        const float4* w2src = (const float4*)W2;
        float4* w2dst = (float4*)s->W2s;
        for (int i = tid; i < HH * HH / 4; i += 512) w2dst[i] = w2src[i];

        if (tid < 2 * H4 / 4) ((float4*)s->Wks)[tid] = ((const float4*)Wk)[tid];
        if (tid < H4 / 4)     ((float4*)s->bs)[tid]  = ((const float4*)bias)[tid];
        if (tid < HH / 4)     ((float4*)s->Vs)[tid]  = ((const float4*)V)[tid];
        if (tid < TT * 2 / 4) ((float4*)s->xs)[tid]  = ((const float4*)(x + (size_t)b * TT * 2))[tid];
        if (tid < HH / 4)     ((float4*)s->hs)[tid]  = ((const float4*)(h0 + (size_t)b * HH))[tid];
        if (tid < HH / 4)     ((float4*)s->cs)[tid]  = ((const float4*)(c0 + (size_t)b * HH))[tid];
        if (tid == 0) { s->ptr0 = 1.0f; s->ptr1 = 1.0f; }
    }
    __syncthreads();

    // persistent per-lane V quad (h = 4*lane .. 4*lane+3)
    const float4 Vr = ((const float4*)s->Vs)[lane];

    // Phase-A layout: q = k-quarter (0..3), j4 = output quad index (0..127)
    const int q  = tid >> 7;
    const int j4 = tid & 127;
    const float* WrB = Wr + (size_t)q * 32 * H4 + j4 * 4;

    for (int step = 0; step < TT; ++step) {
        // ---- Phase A: z partials, h @ Wr  (Wr streamed from L2, float4) ----
        {
            const float* hp = s->hs + q * 32;
            const float* wp = WrB;
            float4 acc = make_float4(0.f, 0.f, 0.f, 0.f);
            #pragma unroll 8
            for (int k = 0; k < 32; ++k) {
                float hk = hp[k];
                float4 w = *(const float4*)wp;
                wp += H4;
                acc.x = fmaf(hk, w.x, acc.x);
                acc.y = fmaf(hk, w.y, acc.y);
                acc.z = fmaf(hk, w.z, acc.z);
                acc.w = fmaf(hk, w.w, acc.w);
            }
            ((float4*)(s->zp + q * H4))[j4] = acc;
        }
        __syncthreads();

        // ---- Phase A2: reduce partials + bias + ptr @ Wk -------------------
        {
            float zj = s->zp[tid] + s->zp[H4 + tid] + s->zp[2 * H4 + tid] + s->zp[3 * H4 + tid];
            zj += s->bs[tid];
            zj = fmaf(s->ptr0, s->Wks[tid], zj);
            zj = fmaf(s->ptr1, s->Wks[H4 + tid], zj);
            s->zs[tid] = zj;
        }
        __syncthreads();

        // ---- Phase B: LSTM gates (i,f,g,o) --------------------------------
        if (tid < HH) {
            float zi = s->zs[tid];
            float zf = s->zs[HH + tid];
            float zg = s->zs[2 * HH + tid];
            float zo = s->zs[3 * HH + tid];
            float ig = sigm_(zi);
            float fg = sigm_(zf);
            float gg = tanh_(zg);
            float og = sigm_(zo);
            float cn = fmaf(fg, s->cs[tid], ig * gg);
            s->cs[tid] = cn;
            s->hs[tid] = og * tanh_(cn);
        }
        __syncthreads();

        // ---- Phase C: a = h @ W2 (W2 in SMEM) ------------------------------
        {
            const float* w2 = s->W2s + q * 32 * HH + j4;
            const float* hp = s->hs + q * 32;
            float acc = 0.f;
            #pragma unroll 8
            for (int k = 0; k < 32; ++k)
                acc = fmaf(hp[k], w2[k * HH], acc);
            s->ap[q * HH + j4] = acc;
        }
        __syncthreads();
        if (tid < HH)
            s->aa[tid] = s->ap[tid] + s->ap[HH + tid] + s->ap[2 * HH + tid] + s->ap[3 * HH + tid];
        __syncthreads();

        // ---- Phase D: scores[t] = sum_h V[h]*tanh(ep[t,h] + a[h]) ----------
        {
            float4 a4 = ((const float4*)s->aa)[lane];
            for (int t = warp; t < TT; t += 16) {
                float4 p = ((const float4*)(s->ep + t * HH))[lane];
                float sv;
                sv = Vr.x * tanh_(p.x + a4.x);
                sv = fmaf(Vr.y, tanh_(p.y + a4.y), sv);
                sv = fmaf(Vr.z, tanh_(p.z + a4.z), sv);
                sv = fmaf(Vr.w, tanh_(p.w + a4.w), sv);
                sv += __shfl_xor_sync(0xffffffffu, sv, 16);
                sv += __shfl_xor_sync(0xffffffffu, sv, 8);
                sv += __shfl_xor_sync(0xffffffffu, sv, 4);
                sv += __shfl_xor_sync(0xffffffffu, sv, 2);
                sv += __shfl_xor_sync(0xffffffffu, sv, 1);
                if (lane == 0) s->sc[t] = sv;
            }
        }
        __syncthreads();

        // ---- Phase E: argmax (first-index tie-break), softmax, output -----
        {
            float v  = (tid < TT) ? s->sc[tid] : -3.4e38f;
            int   ix = tid;
            #pragma unroll
            for (int off = 16; off; off >>= 1) {
                float v2 = __shfl_xor_sync(0xffffffffu, v, off);
                int   i2 = __shfl_xor_sync(0xffffffffu, ix, off);
                if (v2 > v || (v2 == v && i2 < ix)) { v = v2; ix = i2; }
            }
            if (lane == 0 && warp < 8) { s->redv[warp] = v; s->redi[warp] = ix; }
            __syncthreads();
            if (tid == 0) {
                float m = s->redv[0]; int mi = s->redi[0];
                #pragma unroll
                for (int qq = 1; qq < 8; ++qq)
                    if (s->redv[qq] > m) { m = s->redv[qq]; mi = s->redi[qq]; }
                s->smax = m;
                s->ptr0 = s->xs[mi * 2];
                s->ptr1 = s->xs[mi * 2 + 1];
            }
            __syncthreads();

            float e = 0.f;
            if (tid < TT) e = ex2f_((s->sc[tid] - s->smax) * 1.4426950408889634f);
            float se = e;
            se += __shfl_xor_sync(0xffffffffu, se, 16);
            se += __shfl_xor_sync(0xffffffffu, se, 8);
            se += __shfl_xor_sync(0xffffffffu, se, 4);
            se += __shfl_xor_sync(0xffffffffu, se, 2);
            se += __shfl_xor_sync(0xffffffffu, se, 1);
            if (lane == 0 && warp < 8) s->redv[warp] = se;
            __syncthreads();
            if (tid == 0) {
                float ssum = 0.f;
                #pragma unroll
                for (int qq = 0; qq < 8; ++qq) ssum += s->redv[qq];
                s->sinv = 1.0f / ssum;
            }
            __syncthreads();
            if (tid < TT)
                out[((size_t)b * TT + step) * TT + tid] = e * s->sinv;
        }
        // no trailing sync needed: next Phase A only reads hs/ptr (fenced above)
        // and writes zp, whose last reader was behind a sync this step.
    }
}

// ---------------- launch ----------------------------------------------------
extern "C" void kernel_launch(void* const* d_in, const int* in_sizes, int n_in,
                              void* d_out, int out_size) {
    const float* x   = (const float*)d_in[0];
    const float* enc = (const float*)d_in[1];
    const float* h0  = (const float*)d_in[2];
    const float* c0  = (const float*)d_in[3];
    const float* W1  = (const float*)d_in[4];
    const float* W2  = (const float*)d_in[5];
    const float* V   = (const float*)d_in[6];
    const float* Wk  = (const float*)d_in[7];
    const float* Wr  = (const float*)d_in[8];
    const float* bia = (const float*)d_in[9];
    float* out = (float*)d_out;

    // opt-in to large dynamic SMEM (idempotent, deterministic)
    cudaFuncSetAttribute(decode_k, cudaFuncAttributeMaxDynamicSharedMemorySize,
                         (int)sizeof(DecodeSmem));

    encproj_k<<<(BB * TT) / 32, 128>>>(enc, W1);
    decode_k<<<BB, 512, sizeof(DecodeSmem)>>>(x, h0, c0, W2, V, Wk, Wr, bia, out);
}

// round 4
// speedup vs baseline: 1.5660x; 1.5660x over previous
#include <cuda_runtime.h>

#define BB 64
#define TT 256
#define HH 128
#define H4 512
#define HT 128   // t-half handled per CTA
#define HZ 256   // z-half handled per CTA

// Precomputed enc_proj = enc_output @ W1, [B*T, H]  (8 MB scratch)
__device__ float g_ep[BB * TT * HH];

// ---------------- fast-but-accurate transcendentals (err ~5e-7 abs) --------
__device__ __forceinline__ float ex2f_(float x) {
    float y; asm("ex2.approx.ftz.f32 %0, %1;" : "=f"(y) : "f"(x)); return y;
}
__device__ __forceinline__ float rcpf_(float x) {
    float y; asm("rcp.approx.ftz.f32 %0, %1;" : "=f"(y) : "f"(x)); return y;
}
__device__ __forceinline__ float tanh_(float x) {
    float ax = fabsf(x);
    float e  = ex2f_(ax * 2.8853900817779268f);   // 2*log2(e)
    float y  = fmaf(-2.0f, rcpf_(e + 1.0f), 1.0f);
    return copysignf(y, x);
}
__device__ __forceinline__ float sigm_(float x) {
    return rcpf_(1.0f + ex2f_(-1.4426950408889634f * x));
}

// ---------------- DSMEM / mbarrier helpers ---------------------------------
__device__ __forceinline__ unsigned smem_u32(const void* p) {
    unsigned a;
    asm("{ .reg .u64 t; cvta.to.shared.u64 t, %1; cvt.u32.u64 %0, t; }"
        : "=r"(a) : "l"(p));
    return a;
}
__device__ __forceinline__ unsigned mapa_u32(unsigned a, unsigned rank) {
    unsigned o; asm("mapa.shared::cluster.u32 %0, %1, %2;" : "=r"(o) : "r"(a), "r"(rank));
    return o;
}
__device__ __forceinline__ void st_rem_f32(unsigned a, float v) {
    asm volatile("st.shared::cluster.f32 [%0], %1;" :: "r"(a), "f"(v) : "memory");
}
__device__ __forceinline__ void mbar_init(unsigned a, unsigned cnt) {
    asm volatile("mbarrier.init.shared.b64 [%0], %1;" :: "r"(a), "r"(cnt) : "memory");
}
__device__ __forceinline__ void mbar_arrive_remote(unsigned a) {
    asm volatile("mbarrier.arrive.release.cluster.shared::cluster.b64 _, [%0];"
                 :: "r"(a) : "memory");
}
__device__ __forceinline__ void mbar_wait_parity(unsigned a, unsigned par) {
    unsigned done;
    do {
        asm volatile(
            "{ .reg .pred p;\n\t"
            "mbarrier.try_wait.parity.acquire.cluster.shared::cta.b64 p, [%1], %2, 0x989680;\n\t"
            "selp.b32 %0, 1, 0, p; }"
            : "=r"(done) : "r"(a), "r"(par) : "memory");
    } while (!done);
}
#define CLUSTER_SYNC_() do { \
    asm volatile("barrier.cluster.arrive.aligned;" ::: "memory"); \
    asm volatile("barrier.cluster.wait.aligned;"   ::: "memory"); \
} while (0)

// ---------------- kernel 1: enc_proj = enc_output @ W1 ---------------------
__global__ void __launch_bounds__(128) encproj_k(const float* __restrict__ enc,
                                                 const float* __restrict__ W1) {
    __shared__ float rowbuf[32 * HH];
    int base = blockIdx.x * 32;
    const float4* src = (const float4*)(enc + (size_t)base * HH);
    float4* dst = (float4*)rowbuf;
    for (int i = threadIdx.x; i < 32 * HH / 4; i += 128) dst[i] = src[i];
    __syncthreads();
    int j = threadIdx.x;
    for (int r = 0; r < 32; ++r) {
        float acc = 0.f;
        #pragma unroll 16
        for (int h = 0; h < HH; ++h)
            acc = fmaf(rowbuf[r * HH + h], __ldg(&W1[h * HH + j]), acc);
        g_ep[(size_t)(base + r) * HH + j] = acc;
    }
}

// ---------------- kernel 2: 2-CTA-cluster per-batch decoder ----------------
struct DecodeSmem {
    unsigned long long mb_z;     // peer's z-half ready (256 arrives/step)
    unsigned long long mb_s;     // peer's score-half ready (128 arrives/step)
    float ep[HT * HH];    // 64 KB: this CTA's t-half of enc_proj
    float W2s[HH * HH];   // 64 KB
    float Wks[2 * H4];    //  4 KB
    float bs[H4];
    float Vs[HH];
    float xs[TT * 2];
    float hs[HH];
    float cs[HH];
    float zp[8 * HZ];     //  8 KB: k-partials for this CTA's z-half
    float zs[H4];         //  full gate pre-activations (both halves)
    float ap[4 * HH];
    float aa[HH];
    float sc[TT];         //  full scores (both halves)
    float redv[16];
    int   redi[16];
    float smax, sinv, ptr0, ptr1;
};

__global__ void __launch_bounds__(512, 1) __cluster_dims__(2, 1, 1)
decode_k(const float* __restrict__ x,   const float* __restrict__ h0,
         const float* __restrict__ c0,  const float* __restrict__ W2,
         const float* __restrict__ V,   const float* __restrict__ Wk,
         const float* __restrict__ Wr,  const float* __restrict__ bias,
         float* __restrict__ out)
{
    extern __shared__ float smraw[];
    DecodeSmem* s = (DecodeSmem*)smraw;

    const int b    = blockIdx.x >> 1;
    unsigned rank; asm("mov.u32 %0, %%cluster_ctarank;" : "=r"(rank));
    const unsigned peer = rank ^ 1u;
    const int tid  = threadIdx.x;
    const int lane = tid & 31;
    const int warp = tid >> 5;

    // ---- prologue: stage reusable data into SMEM ---------------------------
    {
        const float4* epsrc = (const float4*)(g_ep + ((size_t)b * TT + rank * HT) * HH);
        float4* epdst = (float4*)s->ep;
        for (int i = tid; i < HT * HH / 4; i += 512) epdst[i] = epsrc[i];

        const float4* w2src = (const float4*)W2;
        float4* w2dst = (float4*)s->W2s;
        for (int i = tid; i < HH * HH / 4; i += 512) w2dst[i] = w2src[i];

        if (tid < 2 * H4 / 4) ((float4*)s->Wks)[tid] = ((const float4*)Wk)[tid];
        if (tid < H4 / 4)     ((float4*)s->bs)[tid]  = ((const float4*)bias)[tid];
        if (tid < HH / 4)     ((float4*)s->Vs)[tid]  = ((const float4*)V)[tid];
        if (tid < TT * 2 / 4) ((float4*)s->xs)[tid]  = ((const float4*)(x + (size_t)b * TT * 2))[tid];
        if (tid < HH / 4)     ((float4*)s->hs)[tid]  = ((const float4*)(h0 + (size_t)b * HH))[tid];
        if (tid < HH / 4)     ((float4*)s->cs)[tid]  = ((const float4*)(c0 + (size_t)b * HH))[tid];
        if (tid == 0) {
            s->ptr0 = 1.0f; s->ptr1 = 1.0f;
            mbar_init(smem_u32(&s->mb_z), HZ);   // 256 arrives per phase
            mbar_init(smem_u32(&s->mb_s), HT);   // 128 arrives per phase
        }
    }
    __syncthreads();
    CLUSTER_SYNC_();   // peer barriers initialized before any remote arrive

    const unsigned mbz_local = smem_u32(&s->mb_z);
    const unsigned mbs_local = smem_u32(&s->mb_s);
    const unsigned mbz_rem   = mapa_u32(mbz_local, peer);
    const unsigned mbs_rem   = mapa_u32(mbs_local, peer);
    const unsigned zs_base   = smem_u32(s->zs);
    const unsigned sc_base   = smem_u32(s->sc);

    const float4 Vr = ((const float4*)s->Vs)[lane];

    // Phase-A layout: kq = k-eighth (0..7), j4 = output quad within our half
    const int kq = tid >> 6;
    const int j4 = tid & 63;
    const float* WrB = Wr + (size_t)kq * 16 * H4 + rank * HZ + j4 * 4;

    for (int step = 0; step < TT; ++step) {
        const unsigned par = step & 1u;

        // ---- Phase A: z-half partials, h @ Wr (our 256 columns) ------------
        {
            const float* hp = s->hs + kq * 16;
            const float* wp = WrB;
            float4 acc = make_float4(0.f, 0.f, 0.f, 0.f);
            #pragma unroll
            for (int k = 0; k < 16; ++k) {
                float hk = hp[k];
                float4 w = *(const float4*)wp;
                wp += H4;
                acc.x = fmaf(hk, w.x, acc.x);
                acc.y = fmaf(hk, w.y, acc.y);
                acc.z = fmaf(hk, w.z, acc.z);
                acc.w = fmaf(hk, w.w, acc.w);
            }
            ((float4*)(s->zp + kq * HZ))[j4] = acc;
        }
        __syncthreads();

        // ---- Phase A2: reduce partials + bias + ptr@Wk; exchange z-half ----
        if (tid < HZ) {
            int jg = rank * HZ + tid;
            float zj = s->zp[tid]          + s->zp[HZ + tid]
                     + s->zp[2 * HZ + tid] + s->zp[3 * HZ + tid]
                     + s->zp[4 * HZ + tid] + s->zp[5 * HZ + tid]
                     + s->zp[6 * HZ + tid] + s->zp[7 * HZ + tid];
            zj += s->bs[jg];
            zj = fmaf(s->ptr0, s->Wks[jg], zj);
            zj = fmaf(s->ptr1, s->Wks[H4 + jg], zj);
            s->zs[jg] = zj;
            st_rem_f32(mapa_u32(zs_base + 4u * jg, peer), zj);
            mbar_arrive_remote(mbz_rem);
        }
        __syncthreads();
        mbar_wait_parity(mbz_local, par);   // peer z-half landed in s->zs

        // ---- Phase B: LSTM gates (redundant, bit-identical in both CTAs) ---
        if (tid < HH) {
            float zi = s->zs[tid];
            float zf = s->zs[HH + tid];
            float zg = s->zs[2 * HH + tid];
            float zo = s->zs[3 * HH + tid];
            float ig = sigm_(zi);
            float fg = sigm_(zf);
            float gg = tanh_(zg);
            float og = sigm_(zo);
            float cn = fmaf(fg, s->cs[tid], ig * gg);
            s->cs[tid] = cn;
            s->hs[tid] = og * tanh_(cn);
        }
        __syncthreads();

        // ---- Phase C: a = h @ W2 (SMEM, redundant in both CTAs) ------------
        {
            const int q = tid >> 7, j = tid & 127;
            const float* w2 = s->W2s + q * 32 * HH + j;
            const float* hp = s->hs + q * 32;
            float acc = 0.f;
            #pragma unroll 8
            for (int k = 0; k < 32; ++k)
                acc = fmaf(hp[k], w2[k * HH], acc);
            s->ap[q * HH + j] = acc;
        }
        __syncthreads();
        if (tid < HH)
            s->aa[tid] = s->ap[tid] + s->ap[HH + tid] + s->ap[2 * HH + tid] + s->ap[3 * HH + tid];
        __syncthreads();

        // ---- Phase D: our 128 scores sc[rank*128 .. +127] -------------------
        {
            float4 a4 = ((const float4*)s->aa)[lane];
            for (int tl = warp; tl < HT; tl += 16) {
                float4 p = ((const float4*)(s->ep + tl * HH))[lane];
                float sv;
                sv = Vr.x * tanh_(p.x + a4.x);
                sv = fmaf(Vr.y, tanh_(p.y + a4.y), sv);
                sv = fmaf(Vr.z, tanh_(p.z + a4.z), sv);
                sv = fmaf(Vr.w, tanh_(p.w + a4.w), sv);
                sv += __shfl_xor_sync(0xffffffffu, sv, 16);
                sv += __shfl_xor_sync(0xffffffffu, sv, 8);
                sv += __shfl_xor_sync(0xffffffffu, sv, 4);
                sv += __shfl_xor_sync(0xffffffffu, sv, 2);
                sv += __shfl_xor_sync(0xffffffffu, sv, 1);
                if (lane == 0) s->sc[rank * HT + tl] = sv;
            }
        }
        __syncthreads();

        // ---- exchange score halves -----------------------------------------
        if (tid < HT) {
            int tg = rank * HT + tid;
            float v = s->sc[tg];
            st_rem_f32(mapa_u32(sc_base + 4u * tg, peer), v);
            mbar_arrive_remote(mbs_rem);
        }
        mbar_wait_parity(mbs_local, par);   // full sc now present in both CTAs

        // ---- Phase E: argmax + softmax (redundant), write our output half --
        {
            float v  = (tid < TT) ? s->sc[tid] : -3.4e38f;
            int   ix = tid;
            #pragma unroll
            for (int off = 16; off; off >>= 1) {
                float v2 = __shfl_xor_sync(0xffffffffu, v, off);
                int   i2 = __shfl_xor_sync(0xffffffffu, ix, off);
                if (v2 > v || (v2 == v && i2 < ix)) { v = v2; ix = i2; }
            }
            if (lane == 0 && warp < 8) { s->redv[warp] = v; s->redi[warp] = ix; }
            __syncthreads();
            if (tid == 0) {
                float m = s->redv[0]; int mi = s->redi[0];
                #pragma unroll
                for (int qq = 1; qq < 8; ++qq)
                    if (s->redv[qq] > m) { m = s->redv[qq]; mi = s->redi[qq]; }
                s->smax = m;
                s->ptr0 = s->xs[mi * 2];
                s->ptr1 = s->xs[mi * 2 + 1];
            }
            __syncthreads();

            float e = 0.f;
            if (tid < TT) e = ex2f_((s->sc[tid] - s->smax) * 1.4426950408889634f);
            float se = e;
            se += __shfl_xor_sync(0xffffffffu, se, 16);
            se += __shfl_xor_sync(0xffffffffu, se, 8);
            se += __shfl_xor_sync(0xffffffffu, se, 4);
            se += __shfl_xor_sync(0xffffffffu, se, 2);
            se += __shfl_xor_sync(0xffffffffu, se, 1);
            if (lane == 0 && warp < 8) s->redv[warp] = se;
            __syncthreads();
            if (tid == 0) {
                float ssum = 0.f;
                #pragma unroll
                for (int qq = 0; qq < 8; ++qq) ssum += s->redv[qq];
                s->sinv = 1.0f / ssum;
            }
            __syncthreads();
            if (tid < TT && (tid >> 7) == (int)rank)
                out[((size_t)b * TT + step) * TT + tid] = e * s->sinv;
        }
        // No trailing sync: next Phase A reads hs/ptr (fenced above) and
        // writes zp, whose last reader (A2) sits behind a sync this step.
        // Cross-CTA buffer reuse is gated: our next remote z/sc writes can't
        // happen until we passed this step's mb_s wait, which required the
        // peer's post-D arrive, which is program-ordered after the peer's
        // reads of zs (Phase B) and writes of sc (Phase D).
    }
    CLUSTER_SYNC_();   // keep SMEM alive until peer's remote ops are done
}

// ---------------- launch ----------------------------------------------------
extern "C" void kernel_launch(void* const* d_in, const int* in_sizes, int n_in,
                              void* d_out, int out_size) {
    const float* x   = (const float*)d_in[0];
    const float* enc = (const float*)d_in[1];
    const float* h0  = (const float*)d_in[2];
    const float* c0  = (const float*)d_in[3];
    const float* W1  = (const float*)d_in[4];
    const float* W2  = (const float*)d_in[5];
    const float* V   = (const float*)d_in[6];
    const float* Wk  = (const float*)d_in[7];
    const float* Wr  = (const float*)d_in[8];
    const float* bia = (const float*)d_in[9];
    float* out = (float*)d_out;

    cudaFuncSetAttribute(decode_k, cudaFuncAttributeMaxDynamicSharedMemorySize,
                         (int)sizeof(DecodeSmem));

    encproj_k<<<(BB * TT) / 32, 128>>>(enc, W1);
    decode_k<<<BB * 2, 512, sizeof(DecodeSmem)>>>(x, h0, c0, W2, V, Wk, Wr, bia, out);
}